// round 9
// baseline (speedup 1.0000x reference)
#include <cuda_runtime.h>
#include <cuda_fp16.h>
#include <cstdint>

#define BATCH 4
#define SEQ   2048
#define CIN   1024
#define HID   1024

// ---------------- scratch (__device__ globals; alloc APIs forbidden) -------
__device__ __half g_q16[BATCH * SEQ * CIN];           // 16 MB
__device__ __half g_k16[BATCH * SEQ * CIN];           // 16 MB
__device__ __half g_v16[BATCH * SEQ * CIN];           // 16 MB
__device__ __half g_WqT[HID * CIN];                   // 2 MB ([h][c])
__device__ __half g_WkT[HID * CIN];                   // 2 MB
__device__ __half g_qp [BATCH * SEQ * HID];           // 16 MB (pre-scaled 2^-5)
__device__ __half g_kp [BATCH * SEQ * HID];           // 16 MB
__device__ __half g_vpT[BATCH * HID * SEQ];           // 16 MB ([b][h][t])
__device__ float  g_S  [(long)BATCH * SEQ * SEQ];     // 64 MB (fp32 logits)
__device__ __half g_P  [(long)BATCH * SEQ * SEQ];     // 32 MB

// ---------------- helpers ---------------------------------------------------
__device__ __forceinline__ uint32_t smem_u32(const void* p) {
    uint32_t r;
    asm("{ .reg .u64 t; cvta.to.shared.u64 t, %1; cvt.u32.u64 %0, t; }"
        : "=r"(r) : "l"(p));
    return r;
}
__device__ __forceinline__ void cpa16(uint32_t dst, const void* src) {
    asm volatile("cp.async.cg.shared.global [%0], [%1], 16;" :: "r"(dst), "l"(src));
}
__device__ __forceinline__ void ldsm4(uint32_t* r, uint32_t addr) {
    asm volatile("ldmatrix.sync.aligned.m8n8.x4.shared.b16 {%0,%1,%2,%3}, [%4];"
                 : "=r"(r[0]), "=r"(r[1]), "=r"(r[2]), "=r"(r[3]) : "r"(addr));
}
__device__ __forceinline__ void mma_f16(float* c, const uint32_t* a,
                                        uint32_t b0, uint32_t b1) {
    asm volatile("mma.sync.aligned.m16n8k16.row.col.f32.f16.f16.f32 "
                 "{%0,%1,%2,%3}, {%4,%5,%6,%7}, {%8,%9}, {%0,%1,%2,%3};"
                 : "+f"(c[0]), "+f"(c[1]), "+f"(c[2]), "+f"(c[3])
                 : "r"(a[0]), "r"(a[1]), "r"(a[2]), "r"(a[3]), "r"(b0), "r"(b1));
}

// ---------------- fp16 NT tensor-core GEMM ----------------------------------
// C[M,N] = A[M,K] @ B[N,K]^T, A/B __half K-contiguous. 128x128 CTA tile,
// BK=64 (128B rows, chunk^(row&7) swizzle), 3-stage cp.async, 4 warps (2x2),
// warp tile 64x64, ldmatrix.x4 fragments, fp32 accumulate.
// EPI: 0 = fp16 C[M,N]; 1 = fp16 transposed C (vpT, via smem bounce);
//      2 = fp32 C[M,N].
#define NSTAGE      3
#define STAGE_BYTES 32768       // A 16KB + B 16KB
#define GEMM_SMEM   (NSTAGE * STAGE_BYTES)   // 98304 B
#define GTHREADS    128

template<int EPI>
__device__ __forceinline__
void gemm16(const __half* __restrict__ A, const __half* __restrict__ B,
            void* __restrict__ Cv, int ldA, int ldB, int ldC,
            int KT, int bm, int bn, float alpha)
{
    extern __shared__ char smc[];
    const uint32_t sbase = smem_u32(smc);
    const int tid  = threadIdx.x;
    const int lane = tid & 31;
    const int wid  = tid >> 5;
    const int wm = (wid >> 1) * 64;
    const int wn = (wid & 1) * 64;
    const int qr = lane >> 2;
    const int qc = lane & 3;

    // loader: thread tid owns gmem row tid of both tiles (128B per stage)
    const __half* Arow = A + (long)(bm * 128 + tid) * ldA;
    const __half* Brow = B + (long)(bn * 128 + tid) * ldB;
    const uint32_t lsw = (uint32_t)(tid & 7);
    const uint32_t adRow = sbase + (uint32_t)tid * 128;

    auto issue_stage = [&](int s) {
        const uint32_t off = (uint32_t)((s % NSTAGE) * STAGE_BYTES);
        const char* ap = (const char*)(Arow + s * 64);
        const char* bp = (const char*)(Brow + s * 64);
        const uint32_t ad = adRow + off;
#pragma unroll
        for (int c = 0; c < 8; c++) {
            const uint32_t cs = ((uint32_t)c ^ lsw) * 16;
            cpa16(ad + cs,          ap + c * 16);
            cpa16(ad + 16384 + cs,  bp + c * 16);
        }
        asm volatile("cp.async.commit_group;" ::: "memory");
    };

    // ldmatrix lane addressing (x4: lanes 0-7 rows+k0, 8-15 rows+8+k0,
    // 16-23 rows+k8, 24-31 rows+8+k8)
    const int l15 = lane & 15;
    const uint32_t lkc = (uint32_t)(lane >> 4);
    uint32_t aOff[4], bOff[4], aSw[4], bSw[4];
#pragma unroll
    for (int i = 0; i < 4; i++) {
        int ra = wm + i * 16 + l15;
        aOff[i] = (uint32_t)ra * 128; aSw[i] = (uint32_t)(ra & 7);
        int rb = wn + i * 16 + l15;
        bOff[i] = 16384u + (uint32_t)rb * 128; bSw[i] = (uint32_t)(rb & 7);
    }

    float acc[4][8][4];
#pragma unroll
    for (int mt = 0; mt < 4; mt++)
#pragma unroll
        for (int nt = 0; nt < 8; nt++)
#pragma unroll
            for (int i = 0; i < 4; i++) acc[mt][nt][i] = 0.0f;

    issue_stage(0);
    issue_stage(1);

    for (int kt = 0; kt < KT; kt++) {
        asm volatile("cp.async.wait_group 1;" ::: "memory");
        __syncthreads();
        const uint32_t stB = sbase + (uint32_t)((kt % NSTAGE) * STAGE_BYTES);

        const int sf = kt + 2;
        if (sf < KT) issue_stage(sf);
        else asm volatile("cp.async.commit_group;" ::: "memory");

#pragma unroll
        for (int ks = 0; ks < 4; ks++) {
            const uint32_t kc = (uint32_t)(ks * 2);
            uint32_t af[4][4], bf[4][4];
#pragma unroll
            for (int i = 0; i < 4; i++)
                ldsm4(af[i], stB + aOff[i] + (((kc + lkc) ^ aSw[i]) * 16));
#pragma unroll
            for (int i = 0; i < 4; i++)
                ldsm4(bf[i], stB + bOff[i] + (((kc + lkc) ^ bSw[i]) * 16));
#pragma unroll
            for (int mt = 0; mt < 4; mt++)
#pragma unroll
                for (int n2 = 0; n2 < 4; n2++) {
                    mma_f16(acc[mt][2 * n2],     af[mt], bf[n2][0], bf[n2][2]);
                    mma_f16(acc[mt][2 * n2 + 1], af[mt], bf[n2][1], bf[n2][3]);
                }
        }
    }

    if (EPI == 2) {                       // fp32 output
        float* C = (float*)Cv;
#pragma unroll
        for (int mt = 0; mt < 4; mt++) {
            int r = bm * 128 + wm + mt * 16 + qr;
#pragma unroll
            for (int nt = 0; nt < 8; nt++) {
                int col = bn * 128 + wn + nt * 8 + 2 * qc;
                *(float2*)&C[(long)r * ldC + col] =
                    make_float2(acc[mt][nt][0], acc[mt][nt][1]);
                *(float2*)&C[(long)(r + 8) * ldC + col] =
                    make_float2(acc[mt][nt][2], acc[mt][nt][3]);
            }
        }
    } else if (EPI == 0) {                // fp16 output [M][N]
        __half* C = (__half*)Cv;
#pragma unroll
        for (int mt = 0; mt < 4; mt++) {
            int r = bm * 128 + wm + mt * 16 + qr;
#pragma unroll
            for (int nt = 0; nt < 8; nt++) {
                int col = bn * 128 + wn + nt * 8 + 2 * qc;
                __half2 h0 = __floats2half2_rn(acc[mt][nt][0] * alpha,
                                               acc[mt][nt][1] * alpha);
                __half2 h1 = __floats2half2_rn(acc[mt][nt][2] * alpha,
                                               acc[mt][nt][3] * alpha);
                *(__half2*)&C[(long)r * ldC + col]       = h0;
                *(__half2*)&C[(long)(r + 8) * ldC + col] = h1;
            }
        }
    } else {                              // fp16 transposed (vpT) via smem
        asm volatile("cp.async.wait_group 0;" ::: "memory");
        __syncthreads();
        __half* sb = (__half*)smc;        // [128 h][136 t] halves
#pragma unroll
        for (int mt = 0; mt < 4; mt++) {
            int t0 = wm + mt * 16 + qr;
#pragma unroll
            for (int nt = 0; nt < 8; nt++) {
                int h = wn + nt * 8 + 2 * qc;
                sb[(h)     * 136 + t0]     = __float2half_rn(acc[mt][nt][0]);
                sb[(h + 1) * 136 + t0]     = __float2half_rn(acc[mt][nt][1]);
                sb[(h)     * 136 + t0 + 8] = __float2half_rn(acc[mt][nt][2]);
                sb[(h + 1) * 136 + t0 + 8] = __float2half_rn(acc[mt][nt][3]);
            }
        }
        __syncthreads();
        // vpT[b][h][t]: batch = bm>>4, t-block = bm&15, h row = bn*128+tid
        __half* C = (__half*)Cv + (long)(bm >> 4) * HID * SEQ
                  + (long)(bn * 128 + tid) * SEQ + (bm & 15) * 128;
        const uint4* src = (const uint4*)(sb + tid * 136);
#pragma unroll
        for (int c = 0; c < 16; c++) ((uint4*)C)[c] = src[c];
    }
}

// qp = q16 @ WqT^T (alpha 2^-5), kp = k16 @ WkT^T
__global__ __launch_bounds__(GTHREADS, 2)
void proj_qk(const __half* __restrict__ q16, const __half* __restrict__ k16,
             const __half* __restrict__ WqT, const __half* __restrict__ WkT,
             __half* __restrict__ qp, __half* __restrict__ kp)
{
    const __half* A; const __half* B; __half* C; float alpha;
    if (blockIdx.z == 0) { A = q16; B = WqT; C = qp; alpha = 1.0f / 32.0f; }
    else                 { A = k16; B = WkT; C = kp; alpha = 1.0f; }
    gemm16<0>(A, B, C, CIN, CIN, HID, CIN / 64, blockIdx.y, blockIdx.x, alpha);
}

// vpT = transpose(v16 @ WqT^T)  (faithful bug: v projected with Wq)
__global__ __launch_bounds__(GTHREADS, 2)
void proj_v(const __half* __restrict__ v16, const __half* __restrict__ WqT,
            __half* __restrict__ vpT)
{
    gemm16<1>(v16, WqT, vpT, CIN, CIN, 0, CIN / 64, blockIdx.y, blockIdx.x, 1.0f);
}

// S = qp @ kp^T (fp32 logits), triangular grid, heavy blocks first.
__global__ __launch_bounds__(GTHREADS, 2)
void s_gemm(const __half* __restrict__ qp, const __half* __restrict__ kp,
            float* __restrict__ S)
{
    int idx = 135 - blockIdx.x;
    int acc = 0, bm = 0;
    while (acc + bm + 1 <= idx) { acc += bm + 1; bm++; }
    int bn = idx - acc;
    const long ob = (long)blockIdx.z * SEQ * HID;
    gemm16<2>(qp + ob, kp + ob, S + (long)blockIdx.z * SEQ * SEQ,
              HID, HID, SEQ, HID / 64, bm, bn, 1.0f);
}

// out = P @ vpT^T, K causally limited, heavy blocks first.
__global__ __launch_bounds__(GTHREADS, 2)
void pv_gemm(const __half* __restrict__ P, const __half* __restrict__ vpT,
             float* __restrict__ out)
{
    const int bm = (int)(gridDim.y - 1 - blockIdx.y);
    const int bn = blockIdx.x;
    const int KT = (bm + 1) * 2;
    gemm16<2>(P + (long)blockIdx.z * SEQ * SEQ,
              vpT + (long)blockIdx.z * HID * SEQ,
              out + (long)blockIdx.z * SEQ * HID,
              SEQ, SEQ, HID, KT, bm, bn, 1.0f);
}

// ---------------- conversions ----------------------------------------------
__global__ __launch_bounds__(256)
void cvt3(const float* __restrict__ q, const float* __restrict__ k,
          const float* __restrict__ v, __half* __restrict__ q16,
          __half* __restrict__ k16, __half* __restrict__ v16)
{
    const float* in = (blockIdx.z == 0) ? q : (blockIdx.z == 1) ? k : v;
    __half* out     = (blockIdx.z == 0) ? q16 : (blockIdx.z == 1) ? k16 : v16;
    long i = ((long)blockIdx.x * 256 + threadIdx.x) * 8;
    float4 a = *(const float4*)(in + i);
    float4 b = *(const float4*)(in + i + 4);
    __half2 h[4] = { __floats2half2_rn(a.x, a.y), __floats2half2_rn(a.z, a.w),
                     __floats2half2_rn(b.x, b.y), __floats2half2_rn(b.z, b.w) };
    *(uint4*)(out + i) = *(uint4*)h;
}

__global__ __launch_bounds__(256)
void wtrans(const float* __restrict__ Wq, const float* __restrict__ Wk,
            __half* __restrict__ WqT, __half* __restrict__ WkT)
{
    const float* W = blockIdx.z ? Wk : Wq;
    __half* O      = blockIdx.z ? WkT : WqT;
    __shared__ float t[32][33];
    const int h0 = blockIdx.x * 32, c0 = blockIdx.y * 32;
    const int tx = threadIdx.x & 31, ty = threadIdx.x >> 5;
#pragma unroll
    for (int i = 0; i < 32; i += 8)
        t[ty + i][tx] = W[(long)(c0 + ty + i) * HID + h0 + tx];
    __syncthreads();
#pragma unroll
    for (int i = 0; i < 32; i += 8)
        O[(long)(h0 + ty + i) * CIN + c0 + tx] = __float2half_rn(t[tx][ty + i]);
}

// ---------------- causal softmax: fp32 logits -> fp16 P --------------------
__global__ __launch_bounds__(256)
void softmax_fast(const float* __restrict__ S, __half* __restrict__ P)
{
    const int t = blockIdx.x, b = blockIdx.y;
    const float* row = S + ((long)b * SEQ + t) * SEQ;
    __half* prow = P + ((long)b * SEQ + t) * SEQ;
    const int n = t + 1;
    const int limit = ((t >> 7) + 1) << 7;
    const int tid = threadIdx.x;
    const int lane = tid & 31, wid = tid >> 5;
    const int i0 = tid * 8;

    __shared__ float redm[8], reds[8];

    float4 v0 = *(const float4*)(row + i0);
    float4 v1 = *(const float4*)(row + i0 + 4);
    float r[8] = { v0.x, v0.y, v0.z, v0.w, v1.x, v1.y, v1.z, v1.w };
#pragma unroll
    for (int j = 0; j < 8; j++) if (i0 + j >= n) r[j] = -1e30f;

    float m = -1e30f;
#pragma unroll
    for (int j = 0; j < 8; j++) m = fmaxf(m, r[j]);
#pragma unroll
    for (int o = 16; o > 0; o >>= 1) m = fmaxf(m, __shfl_xor_sync(~0u, m, o));
    if (lane == 0) redm[wid] = m;
    __syncthreads();
#pragma unroll
    for (int j = 0; j < 8; j++) m = fmaxf(m, redm[j]);

    float sum = 0.0f;
#pragma unroll
    for (int j = 0; j < 8; j++) { r[j] = __expf(r[j] - m); sum += r[j]; }
#pragma unroll
    for (int o = 16; o > 0; o >>= 1) sum += __shfl_xor_sync(~0u, sum, o);
    if (lane == 0) reds[wid] = sum;
    __syncthreads();
    sum = 0.0f;
#pragma unroll
    for (int j = 0; j < 8; j++) sum += reds[j];
    const float inv = 1.0f / sum;

    if (i0 < limit) {
        __half2 h[4];
#pragma unroll
        for (int j = 0; j < 4; j++) {
            float a = (i0 + 2 * j     < n) ? r[2 * j]     * inv : 0.0f;
            float c = (i0 + 2 * j + 1 < n) ? r[2 * j + 1] * inv : 0.0f;
            h[j] = __floats2half2_rn(a, c);
        }
        *(uint4*)(prow + i0) = *(uint4*)h;
    }
}

// ---------------- launch ---------------------------------------------------
extern "C" void kernel_launch(void* const* d_in, const int* in_sizes, int n_in,
                              void* d_out, int out_size)
{
    const float* kin = (const float*)d_in[1];
    const float* qin = (const float*)d_in[2];
    const float* vin = (const float*)d_in[3];
    const float* Wk  = (const float*)d_in[4];
    const float* Wq  = (const float*)d_in[5];
    float* out = (float*)d_out;

    __half *q16, *k16, *v16, *WqT, *WkT, *qp, *kp, *vpT, *P;
    float *S;
    cudaGetSymbolAddress((void**)&q16, g_q16);
    cudaGetSymbolAddress((void**)&k16, g_k16);
    cudaGetSymbolAddress((void**)&v16, g_v16);
    cudaGetSymbolAddress((void**)&WqT, g_WqT);
    cudaGetSymbolAddress((void**)&WkT, g_WkT);
    cudaGetSymbolAddress((void**)&qp,  g_qp);
    cudaGetSymbolAddress((void**)&kp,  g_kp);
    cudaGetSymbolAddress((void**)&vpT, g_vpT);
    cudaGetSymbolAddress((void**)&S,   g_S);
    cudaGetSymbolAddress((void**)&P,   g_P);

    cudaFuncSetAttribute(proj_qk, cudaFuncAttributeMaxDynamicSharedMemorySize, GEMM_SMEM);
    cudaFuncSetAttribute(proj_v,  cudaFuncAttributeMaxDynamicSharedMemorySize, GEMM_SMEM);
    cudaFuncSetAttribute(s_gemm,  cudaFuncAttributeMaxDynamicSharedMemorySize, GEMM_SMEM);
    cudaFuncSetAttribute(pv_gemm, cudaFuncAttributeMaxDynamicSharedMemorySize, GEMM_SMEM);

    const int M = BATCH * SEQ;                 // 8192
    dim3 blk(256);
    dim3 gblk(GTHREADS);

    // fp16 conversions
    cvt3<<<dim3((M * CIN) / (256 * 8), 1, 3), blk>>>(qin, kin, vin, q16, k16, v16);
    wtrans<<<dim3(HID / 32, CIN / 32, 2), blk>>>(Wq, Wk, WqT, WkT);

    // projections
    proj_qk<<<dim3(HID / 128, M / 128, 2), gblk, GEMM_SMEM>>>(q16, k16, WqT, WkT, qp, kp);
    proj_v <<<dim3(HID / 128, M / 128, 1), gblk, GEMM_SMEM>>>(v16, WqT, vpT);

    // S = qp @ kp^T (fp32 logits)
    s_gemm<<<dim3(136, 1, BATCH), gblk, GEMM_SMEM>>>(qp, kp, S);

    // softmax -> fp16 P
    softmax_fast<<<dim3(SEQ, BATCH), blk>>>(S, P);

    // out = P @ vpT^T
    pv_gemm<<<dim3(HID / 128, SEQ / 128, BATCH), gblk, GEMM_SMEM>>>(P, vpT, out);
}

// round 10
// speedup vs baseline: 1.2784x; 1.2784x over previous
#include <cuda_runtime.h>
#include <cstdint>

#define BATCH 4
#define SEQ   2048
#define CIN   1024
#define HID   1024

// ---------------- scratch (__device__ globals; alloc APIs forbidden) -------
__device__ float g_qp [BATCH * SEQ * HID];          // 32 MB (tf32-rounded, pre-scaled 2^-5)
__device__ float g_kp [BATCH * SEQ * HID];          // 32 MB (tf32-rounded)
__device__ float g_vp [BATCH * SEQ * HID];          // 32 MB (tf32-rounded)
__device__ float g_S  [(long)BATCH * SEQ * SEQ];    // 64 MB

// ---------------- helpers ---------------------------------------------------
__device__ __forceinline__ uint32_t smem_u32(const void* p) {
    uint32_t r;
    asm("{ .reg .u64 t; cvta.to.shared.u64 t, %1; cvt.u32.u64 %0, t; }"
        : "=r"(r) : "l"(p));
    return r;
}
__device__ __forceinline__ void cpa16(uint32_t dst, const void* src) {
    asm volatile("cp.async.cg.shared.global [%0], [%1], 16;" :: "r"(dst), "l"(src));
}
__device__ __forceinline__ uint32_t f2tf(float x) {
    uint32_t r;
    asm("cvt.rna.tf32.f32 %0, %1;" : "=r"(r) : "f"(x));
    return r;
}
__device__ __forceinline__ float roundtf(float x) { return __uint_as_float(f2tf(x)); }
__device__ __forceinline__ void mma_tf32(float* c, const uint32_t* a, const uint32_t* b) {
    asm volatile("mma.sync.aligned.m16n8k8.row.col.f32.tf32.tf32.f32 "
                 "{%0,%1,%2,%3}, {%4,%5,%6,%7}, {%8,%9}, {%0,%1,%2,%3};"
                 : "+f"(c[0]), "+f"(c[1]), "+f"(c[2]), "+f"(c[3])
                 : "r"(a[0]), "r"(a[1]), "r"(a[2]), "r"(a[3]),
                   "r"(b[0]), "r"(b[1]));
}

// ---------------- tensor-core tf32 GEMM core --------------------------------
// C[M,N] = A[M,K] @ Bop, 128x128 CTA tile, BK=32, 3-stage cp.async pipeline,
// 4 warps (2x2), warp tile 64x64, double-buffered fragments.
//   BNN=false: Bop = B[N,K]^T (B row-major K-contiguous).
//   BNN=true : Bop = B[K,N]   (B row-major N-contiguous).
#define NSTAGE      3
#define STAGE_FLTS  8192          // A 4096 + B 4096 floats (32 KB)
#define GEMM_SMEM   (NSTAGE * STAGE_FLTS * 4)   // 98304 B
#define GTHREADS    128

template<bool CVTA, bool ROUND_OUT, bool BNN>
__device__ __forceinline__
void gemm_body(const float* __restrict__ A, const float* __restrict__ B,
               float* __restrict__ C, int ldA, int ldB, int ldC,
               int KT, int bm, int bn, float alphaOut)
{
    extern __shared__ float sm[];
    const uint32_t sbase = smem_u32(sm);
    const int tid  = threadIdx.x;
    const int lane = tid & 31;
    const int wid  = tid >> 5;        // 0..3
    const int wm = (wid >> 1) * 64;
    const int wn = (wid & 1) * 64;
    const int qr = lane >> 2;         // 0..7
    const int qc = lane & 3;          // 0..3
    const int xm = qr << 2;

    // ---- loader bases (strength-reduced) ----
    const int arow = tid >> 3;            // 0..15
    const int akq  = (tid & 7) * 4;
    const float* Abase = A + (long)(bm * 128 + arow) * ldA + akq;
    const long aStride = (long)16 * ldA;
    const uint32_t adst0 = sbase + (uint32_t)(arow * 32 + (akq ^ ((arow & 7) << 2))) * 4;

    const float* Bbase; long bStride; long bStageStep; uint32_t bdst0;
    if (BNN) {   // tile [k][n], swizzle n^=((k&3)<<3)
        const int bk  = tid >> 5;         // 0..3
        const int bn4 = (tid & 31) * 4;
        Bbase = B + (long)bk * ldB + bn * 128 + bn4;
        bStride = (long)4 * ldB;
        bStageStep = (long)32 * ldB;
        bdst0 = sbase + 16384u + (uint32_t)(bk * 128 + (bn4 ^ ((bk & 3) << 3))) * 4;
    } else {     // tile [n][k], same geometry as A
        Bbase = B + (long)(bn * 128 + arow) * ldB + akq;
        bStride = (long)16 * ldB;
        bStageStep = 32;
        bdst0 = sbase + 16384u + (uint32_t)(arow * 32 + (akq ^ ((arow & 7) << 2))) * 4;
    }

    auto issue_stage = [&](int s) {
        const uint32_t soff = (uint32_t)((s % NSTAGE) * (STAGE_FLTS * 4));
        const float* ap = Abase + s * 32;
        uint32_t ad = adst0 + soff;
#pragma unroll
        for (int t = 0; t < 8; t++) { cpa16(ad, ap); ap += aStride; ad += 2048; }
        const float* bp = Bbase + s * bStageStep;
        uint32_t bd = bdst0 + soff;
#pragma unroll
        for (int t = 0; t < 8; t++) { cpa16(bd, bp); bp += bStride; bd += 2048; }
    };

    // NN fragment column pre-swizzle
    int npr[8];
    if (BNN) {
#pragma unroll
        for (int nt = 0; nt < 8; nt++)
            npr[nt] = (wn + nt * 8 + qr) ^ (qc << 3);
    }

    auto load_frags = [&](const float* As, const float* Bs, int ks,
                          uint32_t af[4][4], uint32_t bf[8][2]) {
        const int k0 = ks * 8;
        const int c0 = (k0 + qc) ^ xm;
        const int c1 = (k0 + 4 + qc) ^ xm;
#pragma unroll
        for (int mt = 0; mt < 4; mt++) {
            int r  = wm + mt * 16 + qr;
            int r8 = r + 8;
            if (CVTA) {
                af[mt][0] = f2tf(As[r  * 32 + c0]);
                af[mt][1] = f2tf(As[r8 * 32 + c0]);
                af[mt][2] = f2tf(As[r  * 32 + c1]);
                af[mt][3] = f2tf(As[r8 * 32 + c1]);
            } else {
                af[mt][0] = __float_as_uint(As[r  * 32 + c0]);
                af[mt][1] = __float_as_uint(As[r8 * 32 + c0]);
                af[mt][2] = __float_as_uint(As[r  * 32 + c1]);
                af[mt][3] = __float_as_uint(As[r8 * 32 + c1]);
            }
        }
#pragma unroll
        for (int nt = 0; nt < 8; nt++) {
            if (BNN) {
                bf[nt][0] = __float_as_uint(Bs[(k0 + qc)     * 128 + npr[nt]]);
                bf[nt][1] = __float_as_uint(Bs[(k0 + 4 + qc) * 128 + npr[nt]]);
            } else {
                int n = wn + nt * 8 + qr;
                bf[nt][0] = __float_as_uint(Bs[n * 32 + c0]);
                bf[nt][1] = __float_as_uint(Bs[n * 32 + c1]);
            }
        }
    };

    float acc[4][8][4];
#pragma unroll
    for (int mt = 0; mt < 4; mt++)
#pragma unroll
        for (int nt = 0; nt < 8; nt++)
#pragma unroll
            for (int i = 0; i < 4; i++) acc[mt][nt][i] = 0.0f;

    auto run_mma = [&](uint32_t af[4][4], uint32_t bf[8][2]) {
#pragma unroll
        for (int mt = 0; mt < 4; mt++)
#pragma unroll
            for (int nt = 0; nt < 8; nt++)
                mma_tf32(acc[mt][nt], af[mt], bf[nt]);
    };

    // prologue: stages 0 and 1
#pragma unroll
    for (int s = 0; s < 2; s++) {
        issue_stage(s);
        asm volatile("cp.async.commit_group;" ::: "memory");
    }

    for (int kt = 0; kt < KT; kt++) {
        asm volatile("cp.async.wait_group 1;" ::: "memory");
        __syncthreads();

        const float* As = sm + (kt % NSTAGE) * STAGE_FLTS;
        const float* Bs = As + 4096;

        uint32_t afA[4][4], bfA[8][2], afB[4][4], bfB[8][2];
        load_frags(As, Bs, 0, afA, bfA);

        // prefetch stage kt+2: gmem loads overlap the whole MMA body
        int sf = kt + 2;
        if (sf < KT) issue_stage(sf);
        asm volatile("cp.async.commit_group;" ::: "memory");

        load_frags(As, Bs, 1, afB, bfB);
        run_mma(afA, bfA);
        load_frags(As, Bs, 2, afA, bfA);
        run_mma(afB, bfB);
        load_frags(As, Bs, 3, afB, bfB);
        run_mma(afA, bfA);
        run_mma(afB, bfB);
    }

#pragma unroll
    for (int mt = 0; mt < 4; mt++) {
        int r = bm * 128 + wm + mt * 16 + qr;
#pragma unroll
        for (int nt = 0; nt < 8; nt++) {
            int col = bn * 128 + wn + nt * 8 + 2 * qc;
            float o0 = acc[mt][nt][0] * alphaOut, o1 = acc[mt][nt][1] * alphaOut;
            float o2 = acc[mt][nt][2] * alphaOut, o3 = acc[mt][nt][3] * alphaOut;
            if (ROUND_OUT) { o0 = roundtf(o0); o1 = roundtf(o1);
                             o2 = roundtf(o2); o3 = roundtf(o3); }
            *(float2*)&C[(long)r * ldC + col]       = make_float2(o0, o1);
            *(float2*)&C[(long)(r + 8) * ldC + col] = make_float2(o2, o3);
        }
    }
}

// q/k projections only (NN: W[C][H] read directly):
// z=0 (q,Wq)->qp (pre-scaled 2^-5), z=1 (k,Wk)->kp.
__global__ __launch_bounds__(GTHREADS, 2)
void proj_qk(const float* __restrict__ qin, const float* __restrict__ kin,
             const float* __restrict__ Wq, const float* __restrict__ Wk,
             float* __restrict__ qp, float* __restrict__ kp)
{
    const float* A; const float* B; float* C; float alpha = 1.0f;
    if (blockIdx.z == 0) { A = qin; B = Wq; C = qp; alpha = 1.0f / 32.0f; }
    else                 { A = kin; B = Wk; C = kp; }
    gemm_body<true, true, true>(A, B, C, CIN, HID, HID, CIN / 32,
                                blockIdx.y, blockIdx.x, alpha);
}

// Merged launch: blockIdx.x < 136 -> S = qp @ kp^T block (triangular grid,
// heavy-first, batch = blockIdx.z); blockIdx.x >= 136 -> proj_v block
// (vp = v @ Wq, faithful bug) filling s_gemm's wave tails. The two halves
// are independent: proj_v reads only kernel inputs; vp is consumed by
// pv_gemm (a later launch).
__global__ __launch_bounds__(GTHREADS, 2)
void s_plus_projv(const float* __restrict__ qp, const float* __restrict__ kp,
                  float* __restrict__ S, const float* __restrict__ vin,
                  const float* __restrict__ Wq, float* __restrict__ vp)
{
    if (blockIdx.x < 136) {
        int idx = 135 - blockIdx.x;       // heavy (high-bm) first
        int acc = 0, bm = 0;
        while (acc + bm + 1 <= idx) { acc += bm + 1; bm++; }
        int bn = idx - acc;
        const long ob = (long)blockIdx.z * SEQ * HID;
        gemm_body<false, false, false>(qp + ob, kp + ob,
                                       S + (long)blockIdx.z * SEQ * SEQ,
                                       HID, HID, SEQ, HID / 32, bm, bn, 1.0f);
    } else {
        int id = (int)(blockIdx.x - 136) + (int)blockIdx.z * 128;  // 0..511
        int bm = id >> 3;                 // 0..63
        int bn = id & 7;                  // 0..7
        gemm_body<true, true, true>(vin, Wq, vp, CIN, HID, HID, CIN / 32,
                                    bm, bn, 1.0f);
    }
}

// out = P @ vp (NN), K causally limited, heavy blocks first.
__global__ __launch_bounds__(GTHREADS, 2)
void pv_gemm(const float* __restrict__ S, const float* __restrict__ vp,
             float* __restrict__ out)
{
    const int bm = (int)(gridDim.y - 1 - blockIdx.y);   // heavy first
    const int bn = blockIdx.x;
    const int KT = (bm + 1) * 4;
    gemm_body<false, false, true>(S + (long)blockIdx.z * SEQ * SEQ,
                                  vp + (long)blockIdx.z * SEQ * HID,
                                  out + (long)blockIdx.z * SEQ * HID,
                                  SEQ, HID, HID, KT, bm, bn, 1.0f);
}

// ---------------- single-pass causal softmax (input pre-scaled) ------------
__global__ __launch_bounds__(256)
void softmax_fast(float* __restrict__ S)
{
    const int t = blockIdx.x, b = blockIdx.y;
    float* row = S + ((long)b * SEQ + t) * SEQ;
    const int n = t + 1;
    const int limit = ((t >> 7) + 1) << 7;
    const int tid = threadIdx.x;
    const int lane = tid & 31, wid = tid >> 5;

    __shared__ float redm[8], reds[8];

    float r[8];
#pragma unroll
    for (int j = 0; j < 8; j++) {
        int i = tid + j * 256;
        r[j] = (i < n) ? row[i] : -1e30f;
    }

    float m = -1e30f;
#pragma unroll
    for (int j = 0; j < 8; j++) m = fmaxf(m, r[j]);
#pragma unroll
    for (int o = 16; o > 0; o >>= 1) m = fmaxf(m, __shfl_xor_sync(~0u, m, o));
    if (lane == 0) redm[wid] = m;
    __syncthreads();
#pragma unroll
    for (int j = 0; j < 8; j++) m = fmaxf(m, redm[j]);

    float sum = 0.0f;
#pragma unroll
    for (int j = 0; j < 8; j++) { r[j] = __expf(r[j] - m); sum += r[j]; }
#pragma unroll
    for (int o = 16; o > 0; o >>= 1) sum += __shfl_xor_sync(~0u, sum, o);
    if (lane == 0) reds[wid] = sum;
    __syncthreads();
    sum = 0.0f;
#pragma unroll
    for (int j = 0; j < 8; j++) sum += reds[j];
    const float inv = 1.0f / sum;

#pragma unroll
    for (int j = 0; j < 8; j++) {
        int i = tid + j * 256;
        if (i < limit) row[i] = (i < n) ? roundtf(r[j] * inv) : 0.0f;
    }
}

// ---------------- launch ---------------------------------------------------
extern "C" void kernel_launch(void* const* d_in, const int* in_sizes, int n_in,
                              void* d_out, int out_size)
{
    const float* kin = (const float*)d_in[1];
    const float* qin = (const float*)d_in[2];
    const float* vin = (const float*)d_in[3];
    const float* Wk  = (const float*)d_in[4];
    const float* Wq  = (const float*)d_in[5];
    float* out = (float*)d_out;

    float *qp, *kp, *vp, *S;
    cudaGetSymbolAddress((void**)&qp, g_qp);
    cudaGetSymbolAddress((void**)&kp, g_kp);
    cudaGetSymbolAddress((void**)&vp, g_vp);
    cudaGetSymbolAddress((void**)&S,  g_S);

    cudaFuncSetAttribute(proj_qk,      cudaFuncAttributeMaxDynamicSharedMemorySize, GEMM_SMEM);
    cudaFuncSetAttribute(s_plus_projv, cudaFuncAttributeMaxDynamicSharedMemorySize, GEMM_SMEM);
    cudaFuncSetAttribute(pv_gemm,      cudaFuncAttributeMaxDynamicSharedMemorySize, GEMM_SMEM);

    const int M = BATCH * SEQ;                 // 8192
    dim3 blk(256);
    dim3 gblk(GTHREADS);

    // q/k projections (v projection rides inside the S launch)
    proj_qk<<<dim3(HID / 128, M / 128, 2), gblk, GEMM_SMEM>>>(qin, kin, Wq, Wk, qp, kp);

    // S = qp @ kp^T fused with proj_v (fills S's wave tails)
    s_plus_projv<<<dim3(136 + 128, 1, BATCH), gblk, GEMM_SMEM>>>(qp, kp, S, vin, Wq, vp);

    // softmax (scale pre-folded into qp), zeros upper triangle per 128-block
    softmax_fast<<<dim3(SEQ, BATCH), blk>>>(S);

    // out = P @ vp, K causally limited
    pv_gemm<<<dim3(HID / 128, SEQ / 128, BATCH), gblk, GEMM_SMEM>>>(S, vp, out);
}